// round 6
// baseline (speedup 1.0000x reference)
#include <cuda_runtime.h>
#include <math.h>

#define MAXN 131072
#define DIM  512
#define HALO 64

// Scratch (no allocations allowed in kernel_launch)
__device__ float g_dot[MAXN];     // f_j . attn_w
__device__ float g_scores[MAXN];  // windowed-mean scores
__device__ float g_gw[MAXN];      // g_j = sum_{i in win(j)} w_i / c_i
__device__ float g_pm[2048];      // per-block partial max
__device__ float g_ps[2048];      // per-block partial sumexp

// ---------------- K1: per-row dot product, one warp per row ----------------
__global__ void k_dot(const float* __restrict__ f, const float* __restrict__ w, int n) {
    int warp = threadIdx.x >> 5;
    int lane = threadIdx.x & 31;
    int row  = blockIdx.x * (blockDim.x >> 5) + warp;
    if (row >= n) return;
    const float4* fr = (const float4*)f + (size_t)row * (DIM / 4);
    const float4* wv = (const float4*)w;
    float s = 0.f;
#pragma unroll
    for (int i = 0; i < DIM / 128; i++) {
        float4 a = __ldcs(&fr[lane + 32 * i]);   // streaming: read-once data
        float4 b = __ldg(&wv[lane + 32 * i]);    // hot: keep in L1
        s += a.x * b.x + a.y * b.y + a.z * b.z + a.w * b.w;
    }
#pragma unroll
    for (int o = 16; o; o >>= 1) s += __shfl_down_sync(0xffffffffu, s, o);
    if (lane == 0) g_dot[row] = s;
}

// ------- K2: windowed-mean scores (shared tile) + per-block softmax partials -------
__global__ void k_scores(int n, const int* __restrict__ kptr, const float* __restrict__ bptr) {
    __shared__ float sh_d[256 + 2 * HALO];
    int t = threadIdx.x;
    int lane = t & 31, warp = t >> 5;
    int base = blockIdx.x * 256;
    // stage g_dot tile + halo into shared (clamped; out-of-range entries unused)
    for (int idx = t; idx < 256 + 2 * HALO; idx += 256) {
        int p = min(max(base - HALO + idx, 0), n - 1);
        sh_d[idx] = g_dot[p];
    }
    __syncthreads();
    int i = base + t;
    int k = *kptr;
    float val = -3.0e38f;
    if (i < n) {
        int lo = max(i - k, 0);
        int hi = min(i + k, n - 1);
        float s = 0.f;
        if (k <= HALO) {
            for (int j = lo; j <= hi; j++) s += sh_d[j - base + HALO];
        } else {
            for (int j = lo; j <= hi; j++) s += g_dot[j];
        }
        val = s / (float)(hi - lo + 1) + bptr[0];
        g_scores[i] = val;
    }
    // warp-level max
    float m = val;
#pragma unroll
    for (int o = 16; o; o >>= 1) m = fmaxf(m, __shfl_xor_sync(0xffffffffu, m, o));
    __shared__ float wm[8];
    if (lane == 0) wm[warp] = m;
    __syncthreads();
    float bmax = wm[0];
#pragma unroll
    for (int q = 1; q < 8; q++) bmax = fmaxf(bmax, wm[q]);
    // warp-level sum of exp
    float e = (i < n) ? __expf(val - bmax) : 0.f;
#pragma unroll
    for (int o = 16; o; o >>= 1) e += __shfl_xor_sync(0xffffffffu, e, o);
    __shared__ float ws[8];
    if (lane == 0) ws[warp] = e;
    __syncthreads();
    if (t == 0) {
        float s = ws[0];
#pragma unroll
        for (int q = 1; q < 8; q++) s += ws[q];
        g_pm[blockIdx.x] = bmax;
        g_ps[blockIdx.x] = s;
    }
}

// --- K3: (fused) per-block redundant softmax merge + w_i out + g_j + zero bag ---
__global__ void k_weights(float* __restrict__ out, int n, const int* __restrict__ kptr, int nb) {
    __shared__ float sm[256];
    __shared__ float ssum[256];
    __shared__ float sh_e[256 + 2 * HALO];
    int t = threadIdx.x;
    // 1) merge the nb softmax partials redundantly in every block
    float m = -3.0e38f, s = 0.f;
    for (int p = t; p < nb; p += 256) {
        float mi = g_pm[p], si = g_ps[p];
        float nm = fmaxf(m, mi);
        s = s * __expf(m - nm) + si * __expf(mi - nm);
        m = nm;
    }
    sm[t] = m; ssum[t] = s;
    __syncthreads();
    for (int o = 128; o; o >>= 1) {
        if (t < o) {
            float m2 = sm[t + o], s2 = ssum[t + o];
            float nm = fmaxf(sm[t], m2);
            ssum[t] = ssum[t] * __expf(sm[t] - nm) + s2 * __expf(m2 - nm);
            sm[t] = nm;
        }
        __syncthreads();
    }
    float M = sm[0];
    float invS = 1.f / ssum[0];
    // 2) stage exp(scores - M) for tile + halo: ONE exp per element
    int base = blockIdx.x * 256;
    for (int idx = t; idx < 256 + 2 * HALO; idx += 256) {
        int p = min(max(base - HALO + idx, 0), n - 1);
        sh_e[idx] = __expf(g_scores[p] - M);
    }
    __syncthreads();
    int i = base + t;
    // zero the FULL bag region out[0:DIM] (blocks 0 and 1 cover all 512)
    if (i < DIM) out[i] = 0.f;
    if (i >= n) return;
    int k = *kptr;
    float wi = sh_e[t + HALO] * invS;
    out[DIM + i] = wi;
    int lo = max(i - k, 0);
    int hi = min(i + k, n - 1);
    float g = 0.f;
    if (k <= HALO) {
        for (int j = lo; j <= hi; j++) {
            int loj = max(j - k, 0);
            int hij = min(j + k, n - 1);
            g += sh_e[j - base + HALO] / (float)(hij - loj + 1);
        }
    } else {
        for (int j = lo; j <= hi; j++) {
            int loj = max(j - k, 0);
            int hij = min(j + k, n - 1);
            g += __expf(g_scores[j] - M) / (float)(hij - loj + 1);
        }
    }
    g_gw[i] = g * invS;
}

// ---------------- K4: bag[c] = sum_j g_j * f[j][c] ----------------
__global__ void k_bag(const float* __restrict__ f, float* __restrict__ out, int n) {
    int c  = threadIdx.x;                     // 512 threads = 512 columns
    int nb = gridDim.x;
    int chunk = (n + nb - 1) / nb;
    int j0 = blockIdx.x * chunk;
    int j1 = min(j0 + chunk, n);
    float acc = 0.f;
    int j = j0;
#pragma unroll 1
    for (; j + 3 < j1; j += 4) {
        float g0 = g_gw[j + 0], g1 = g_gw[j + 1], g2 = g_gw[j + 2], g3 = g_gw[j + 3];
        float f0 = __ldcs(&f[(size_t)(j + 0) * DIM + c]);
        float f1 = __ldcs(&f[(size_t)(j + 1) * DIM + c]);
        float f2 = __ldcs(&f[(size_t)(j + 2) * DIM + c]);
        float f3 = __ldcs(&f[(size_t)(j + 3) * DIM + c]);
        acc += g0 * f0 + g1 * f1 + g2 * f2 + g3 * f3;
    }
    for (; j < j1; j++) acc += g_gw[j] * __ldcs(&f[(size_t)j * DIM + c]);
    atomicAdd(&out[c], acc);
}

extern "C" void kernel_launch(void* const* d_in, const int* in_sizes, int n_in,
                              void* d_out, int out_size) {
    const float* features = (const float*)d_in[0];
    const float* attn_w   = (const float*)d_in[1];
    const float* attn_b   = (const float*)d_in[2];
    const int*   kptr     = (const int*)d_in[3];
    float* out = (float*)d_out;

    int d = in_sizes[1];            // 512
    int n = in_sizes[0] / d;        // 100000
    (void)n_in; (void)out_size;

    // K1: dots — 8 warps/block, 1 warp/row
    {
        int rows_per_block = 8;
        int nb = (n + rows_per_block - 1) / rows_per_block;
        k_dot<<<nb, 256>>>(features, attn_w, n);
    }
    // K2: scores + softmax partials
    int nb2 = (n + 255) / 256;
    k_scores<<<nb2, 256>>>(n, kptr, attn_b);
    // K3: fused merge + weights + g + zero bag
    k_weights<<<nb2, 256>>>(out, n, kptr, nb2);
    // K4: weighted column sum
    k_bag<<<592, DIM>>>(features, out, n);
}